// round 1
// baseline (speedup 1.0000x reference)
#include <cuda_runtime.h>
#include <math_constants.h>

#define DIMS     32
#define BINS     1024
#define KCELLS   1024
#define QSTRIDE  1057      // 1024 quantiles + 33 pad (+inf); bank = (d+m)&31
#define CTSTRIDE 1026      // u16 stride; bank gets +d term
#define THREADS  512

// ---------------- device-global scratch (allowed; no allocation) -------------
__device__ unsigned short g_ct[DIMS * KCELLS];  // exclusive prefix: #{q_j : cell_j < c}
__device__ float g_scale[DIMS];
__device__ float g_beta[DIMS];
__device__ int   g_deep;                        // 1 -> fall back to full binary search

// Cell map. MUST be bit-identical between prep and main kernels (same function,
// same fmaf/floor/clamp sequence) so the window-containment proof holds.
__device__ __forceinline__ int cell_of(float v, float sc, float be) {
    float cf = fmaf(v, sc, be);
    int c = __float2int_rd(cf);           // saturating floor-convert
    c = max(c, 0);
    c = min(c, KCELLS - 1);
    return c;
}

// ---------------- prep: per-dim cell table (1 block, 32 warps) ---------------
__global__ void prep_kernel(const float* __restrict__ q) {
    extern __shared__ int hist[];         // DIMS * KCELLS ints = 128 KB
    __shared__ int smax[DIMS];
    const int tid  = threadIdx.x;
    const int d    = tid >> 5;            // warp w handles dim d=w
    const int lane = tid & 31;

    int* h = hist + d * KCELLS;
    const float lo = q[0 * DIMS + d];
    const float hi = q[(BINS - 1) * DIMS + d];
    const float range = hi - lo;
    const float sc = (range > 0.0f) ? ((float)KCELLS / range) : 0.0f;
    const float be = -lo * sc;

    for (int c = lane; c < KCELLS; c += 32) h[c] = 0;
    __syncwarp();
    for (int k = lane; k < BINS; k += 32) {
        float val = q[k * DIMS + d];
        atomicAdd(&h[cell_of(val, sc, be)], 1);
    }
    __syncwarp();

    // exclusive scan of the 1024-bin histogram (warp-sequential in 32 chunks)
    int running = 0, mx = 0;
    for (int base = 0; base < KCELLS; base += 32) {
        int v = h[base + lane];
        mx = max(mx, v);
        int s = v;
        #pragma unroll
        for (int off = 1; off < 32; off <<= 1) {
            int t = __shfl_up_sync(0xffffffffu, s, off);
            if (lane >= off) s += t;
        }
        g_ct[d * KCELLS + base + lane] = (unsigned short)(running + s - v);
        running += __shfl_sync(0xffffffffu, s, 31);
    }
    #pragma unroll
    for (int off = 16; off; off >>= 1)
        mx = max(mx, __shfl_xor_sync(0xffffffffu, mx, off));
    if (lane == 0) { g_scale[d] = sc; g_beta[d] = be; smax[d] = mx; }
    __syncthreads();
    if (tid == 0) {
        int m = 0;
        #pragma unroll
        for (int i = 0; i < DIMS; i++) m = max(m, smax[i]);
        g_deep = (m > 31) ? 1 : 0;        // window-32 fast path valid iff max cnt <= 31
    }
}

// ---------------- search primitives -----------------------------------------
// Counting lower_bound over a 32-wide window starting at ct[c]: answer is
// provably in [start, start+cnt] with cnt<=31 (checked by prep). Probes use
// immediate offsets: LDS+FSETP+@p IADD per level.
__device__ __forceinline__ float fast_lookup(float v, const float* __restrict__ qb,
                                             const unsigned short* __restrict__ ct,
                                             float sc, float be,
                                             const float* __restrict__ ZL) {
    int c = cell_of(v, sc, be);
    const float* p = qb + ct[c];
    if (p[15] < v) p += 16;
    if (p[7]  < v) p += 8;
    if (p[3]  < v) p += 4;
    if (p[1]  < v) p += 2;
    if (p[0]  < v) p += 1;
    int idx = (int)(p - qb);
    idx += (p[0] < v) ? 1 : 0;            // fixup -> exact searchsorted(left)
    return ZL[idx];
}

// Guaranteed-correct full search [0,1024] (used only if g_deep set by prep).
__device__ __forceinline__ float deep_lookup(float v, const float* __restrict__ qb,
                                             const float* __restrict__ ZL) {
    const float* p = qb;
    if (p[511] < v) p += 512;
    if (p[255] < v) p += 256;
    if (p[127] < v) p += 128;
    if (p[63]  < v) p += 64;
    if (p[31]  < v) p += 32;
    if (p[15]  < v) p += 16;
    if (p[7]   < v) p += 8;
    if (p[3]   < v) p += 4;
    if (p[1]   < v) p += 2;
    if (p[0]   < v) p += 1;
    int idx = (int)(p - qb);
    idx += (p[0] < v) ? 1 : 0;
    return ZL[idx];
}

// ---------------- main kernel ------------------------------------------------
#define SMEM_Q   (DIMS * QSTRIDE * 4)                 // 135296 B
#define SMEM_CT  (DIMS * CTSTRIDE * 2)                // 65664 B
#define SMEM_ZL  ((BINS + 1) * 4)                     // 4100 B
#define SMEM_MISC (2 * DIMS * 4 + 64)
#define SMEM_MAIN (SMEM_Q + SMEM_CT + SMEM_ZL + SMEM_MISC)

__global__ void __launch_bounds__(THREADS, 1)
cdf_kernel(const float4* __restrict__ X, const float* __restrict__ q,
           float4* __restrict__ O, int total4) {
    extern __shared__ float smem[];
    float* Qs = smem;                                          // [DIMS][QSTRIDE]
    unsigned short* CT = (unsigned short*)(Qs + DIMS * QSTRIDE);
    float* ZL = (float*)((char*)CT + SMEM_CT);                 // [BINS+1]
    float* SC = ZL + (BINS + 1);
    float* BE = SC + DIMS;
    const int tid = threadIdx.x;

    // transpose quantiles [m][d] -> smem [d][m] (coalesced reads)
    for (int i = tid; i < BINS * DIMS; i += THREADS) {
        int m = i >> 5, d = i & 31;
        Qs[d * QSTRIDE + m] = q[i];
    }
    // +inf pad so window probes past the end are harmless
    for (int i = tid; i < DIMS * (QSTRIDE - BINS); i += THREADS) {
        int d = i / (QSTRIDE - BINS);
        int m = BINS + (i - d * (QSTRIDE - BINS));
        Qs[d * QSTRIDE + m] = CUDART_INF_F;
    }
    // cell-start table
    for (int i = tid; i < DIMS * KCELLS; i += THREADS) {
        int d = i >> 10, c = i & (KCELLS - 1);
        CT[d * CTSTRIDE + c] = g_ct[i];
    }
    // z lookup table: z = erfinv(2*clip(idx/1023)-1)*sqrt2
    for (int i = tid; i <= BINS; i += THREADS) {
        float u = (float)i * (1.0f / (float)(BINS - 1));
        u = fminf(fmaxf(u, 1e-6f), 1.0f - 1e-6f);
        ZL[i] = erfinvf(2.0f * u - 1.0f) * 1.41421356f;
    }
    if (tid < DIMS) { SC[tid] = g_scale[tid]; BE[tid] = g_beta[tid]; }
    __syncthreads();

    const int i0 = blockIdx.x * THREADS + tid;
    const int stride = gridDim.x * THREADS;     // multiple of 512 -> d0 fixed per thread
    const int d0 = (i0 << 2) & 31;

    const float* qb0 = Qs + (d0 + 0) * QSTRIDE;
    const float* qb1 = qb0 + QSTRIDE;
    const float* qb2 = qb1 + QSTRIDE;
    const float* qb3 = qb2 + QSTRIDE;
    const unsigned short* ct0 = CT + (d0 + 0) * CTSTRIDE;
    const unsigned short* ct1 = ct0 + CTSTRIDE;
    const unsigned short* ct2 = ct1 + CTSTRIDE;
    const unsigned short* ct3 = ct2 + CTSTRIDE;
    const float sc0 = SC[d0 + 0], sc1 = SC[d0 + 1], sc2 = SC[d0 + 2], sc3 = SC[d0 + 3];
    const float be0 = BE[d0 + 0], be1 = BE[d0 + 1], be2 = BE[d0 + 2], be3 = BE[d0 + 3];

    if (i0 >= total4) return;

    if (!g_deep) {
        float4 cur = X[i0];
        for (int i = i0; i < total4; i += stride) {
            const int inx = i + stride;
            float4 nxt = cur;
            if (inx < total4) nxt = X[inx];   // prefetch next iteration
            float4 zv;
            zv.x = fast_lookup(cur.x, qb0, ct0, sc0, be0, ZL);
            zv.y = fast_lookup(cur.y, qb1, ct1, sc1, be1, ZL);
            zv.z = fast_lookup(cur.z, qb2, ct2, sc2, be2, ZL);
            zv.w = fast_lookup(cur.w, qb3, ct3, sc3, be3, ZL);
            O[i] = zv;
            cur = nxt;
        }
    } else {
        float4 cur = X[i0];
        for (int i = i0; i < total4; i += stride) {
            const int inx = i + stride;
            float4 nxt = cur;
            if (inx < total4) nxt = X[inx];
            float4 zv;
            zv.x = deep_lookup(cur.x, qb0, ZL);
            zv.y = deep_lookup(cur.y, qb1, ZL);
            zv.z = deep_lookup(cur.z, qb2, ZL);
            zv.w = deep_lookup(cur.w, qb3, ZL);
            O[i] = zv;
            cur = nxt;
        }
    }
}

// ---------------- launch ------------------------------------------------------
extern "C" void kernel_launch(void* const* d_in, const int* in_sizes, int n_in,
                              void* d_out, int out_size) {
    const float* x = (const float*)d_in[0];
    const float* q = (const float*)d_in[1];
    float* out = (float*)d_out;
    const int total  = in_sizes[0];
    const int total4 = total >> 2;

    cudaFuncSetAttribute(prep_kernel, cudaFuncAttributeMaxDynamicSharedMemorySize,
                         DIMS * KCELLS * (int)sizeof(int));
    cudaFuncSetAttribute(cdf_kernel, cudaFuncAttributeMaxDynamicSharedMemorySize,
                         SMEM_MAIN);

    int dev = 0;
    cudaGetDevice(&dev);
    int nsm = 148;
    cudaDeviceGetAttribute(&nsm, cudaDevAttrMultiProcessorCount, dev);

    prep_kernel<<<1, 1024, DIMS * KCELLS * (int)sizeof(int)>>>(q);
    cdf_kernel<<<nsm, THREADS, SMEM_MAIN>>>((const float4*)x, q, (float4*)out, total4);
}

// round 3
// speedup vs baseline: 1.2968x; 1.2968x over previous
#include <cuda_runtime.h>
#include <math_constants.h>

#define DIMS      32
#define BINS      1024
#define KCELLS    1728            // cells per dim
#define GROUP_D   8               // dims per block (4-way split)
#define THREADS   1024

// ---------------- device-global scratch (static; no allocation) --------------
__device__ float4 g_payload[DIMS * KCELLS];   // per (dim, cell) resolving payload
__device__ float  g_qT[DIMS * BINS];          // transposed quantiles (fallback scans)
__device__ float  g_zl[BINS + 1];             // z(idx) lookup
__device__ float  g_scale[DIMS];
__device__ float  g_beta[DIMS];

// Cell map: MUST be bit-identical in prep and main (monotone in v).
__device__ __forceinline__ int cell_of(float v, float sc, float be) {
    float cf = fmaf(v, sc, be);
    int c = __float2int_rd(cf);       // saturating floor-convert
    c = max(c, 0);
    return min(c, KCELLS - 1);
}

// z(idx) = erfinv(2*clip(idx/1023, eps, 1-eps) - 1) * sqrt(2)
__device__ __forceinline__ float zval(int i) {
    float u = (float)i * (1.0f / (float)(BINS - 1));
    u = fminf(fmaxf(u, 1e-6f), 1.0f - 1e-6f);
    return erfinvf(2.0f * u - 1.0f) * 1.41421356f;
}

// ---------------- prep: one block per dim ------------------------------------
// Builds, for dim d: histogram of quantiles over KCELLS uniform cells,
// exclusive prefix (start), then the 16B payload per cell:
//   cnt<=1 : {t0, z_lo, z_hi, int(start)}            (w3 >= 0)
//   cnt>=2 : {t0, t1, t2, 0x80000000|cnt<<16|start}  (w3 <  0)
// t_j = +inf for j >= cnt so compares are safely "false".
__global__ void prep_kernel(const float* __restrict__ q) {
    __shared__ int hist[KCELLS];
    __shared__ int startS[KCELLS];
    const int d   = blockIdx.x;
    const int tid = threadIdx.x;

    const float lo = q[d];
    const float hi = q[(BINS - 1) * DIMS + d];
    const float range = hi - lo;
    const float sc = (range > 0.0f) ? ((float)KCELLS / range) : 0.0f;
    const float be = -lo * sc;

    for (int c = tid; c < KCELLS; c += blockDim.x) hist[c] = 0;
    __syncthreads();
    for (int j = tid; j < BINS; j += blockDim.x) {
        float val = q[j * DIMS + d];
        g_qT[d * BINS + j] = val;            // transposed copy for fallback
        atomicAdd(&hist[cell_of(val, sc, be)], 1);
    }
    // block 0 also fills the global Z-LUT
    if (d == 0) {
        for (int i = tid; i <= BINS; i += blockDim.x) g_zl[i] = zval(i);
    }
    __syncthreads();

    // exclusive scan over KCELLS by warp 0 (chunked warp scan)
    if (tid < 32) {
        int running = 0;
        for (int base = 0; base < KCELLS; base += 32) {
            int v = hist[base + tid];
            int s = v;
            #pragma unroll
            for (int off = 1; off < 32; off <<= 1) {
                int t = __shfl_up_sync(0xffffffffu, s, off);
                if (tid >= off) s += t;
            }
            startS[base + tid] = running + s - v;
            running += __shfl_sync(0xffffffffu, s, 31);
        }
    }
    __syncthreads();

    float4* __restrict__ pay = g_payload + d * KCELLS;
    for (int c = tid; c < KCELLS; c += blockDim.x) {
        int st = startS[c];
        int cn = hist[c];
        float4 pl;
        if (cn <= 1) {
            pl.x = cn ? q[st * DIMS + d] : CUDART_INF_F;
            pl.y = zval(st);
            pl.z = zval(st + cn);
            pl.w = __int_as_float(st);
        } else {
            pl.x = q[st * DIMS + d];
            pl.y = q[(st + 1) * DIMS + d];
            pl.z = (cn > 2) ? q[(st + 2) * DIMS + d] : CUDART_INF_F;
            pl.w = __int_as_float((int)(0x80000000u | ((unsigned)cn << 16) | (unsigned)st));
        }
        pay[c] = pl;
    }
    if (tid == 0) { g_scale[d] = sc; g_beta[d] = be; }
}

// ---------------- main kernel -------------------------------------------------
#define SMEM_PAY  (GROUP_D * KCELLS * 16)             // 221184 B
#define SMEM_ZL   ((BINS + 1) * 4)                    // 4100 B
#define SMEM_MISC (2 * GROUP_D * 4)
#define SMEM_MAIN (SMEM_PAY + SMEM_ZL + SMEM_MISC)

__device__ __forceinline__ float resolve(float v, const float4* __restrict__ P,
                                         float sc, float be,
                                         const float* __restrict__ ZL,
                                         const float* __restrict__ qTd) {
    int c = cell_of(v, sc, be);
    float4 p = P[c];
    int s0 = (p.x < v) ? 1 : 0;
    int w3 = __float_as_int(p.w);
    float z;
    if (w3 >= 0) {                               // cnt <= 1: fully resolved
        z = s0 ? p.z : p.y;
    } else {                                     // cnt >= 2
        int start = w3 & 0xFFF;
        int cnt   = (w3 >> 16) & 0x7FF;
        int idx = start + s0 + ((p.y < v) ? 1 : 0) + ((p.z < v) ? 1 : 0);
        if (idx == start + 3 && cnt > 3) {       // rare: scan remainder (L2)
            int lim = start + cnt;
            while (idx < lim && qTd[idx] < v) idx++;
        }
        z = ZL[idx];
    }
    return z;
}

__global__ void __launch_bounds__(THREADS, 1)
cdf_kernel(const float2* __restrict__ X, float2* __restrict__ O, int nrows) {
    extern __shared__ float smem[];
    float4* PAY = (float4*)smem;                              // [GROUP_D][KCELLS]
    float*  ZL  = (float*)(smem + GROUP_D * KCELLS * 4);      // [BINS+1]
    float*  SC  = ZL + (BINS + 1);
    float*  BE  = SC + GROUP_D;

    const int tid = threadIdx.x;
    const int g   = blockIdx.x & 3;           // dim group: dims [8g, 8g+8)
    const int grp = blockIdx.x >> 2;          // row-group index

    // stage this group's payload slice (coalesced global -> smem)
    {
        const float4* src = g_payload + (GROUP_D * g) * KCELLS;
        for (int i = tid; i < GROUP_D * KCELLS; i += THREADS) PAY[i] = src[i];
    }
    for (int i = tid; i <= BINS; i += THREADS) ZL[i] = g_zl[i];
    if (tid < GROUP_D) {
        SC[tid] = g_scale[GROUP_D * g + tid];
        BE[tid] = g_beta[GROUP_D * g + tid];
    }
    __syncthreads();

    // thread -> (row, float2-column within group's 32B sector)
    const int colq  = tid & 3;                 // 0..3 : which float2 of the sector
    const int rowo  = tid >> 2;                // 0..255
    const int dl    = 2 * colq;                // local dim 0..6 (even)
    const int d0    = GROUP_D * g + dl;        // global dim

    const float4* P0 = PAY + dl * KCELLS;
    const float4* P1 = P0 + KCELLS;
    const float sc0 = SC[dl], sc1 = SC[dl + 1];
    const float be0 = BE[dl], be1 = BE[dl + 1];
    const float* qT0 = g_qT + d0 * BINS;
    const float* qT1 = qT0 + BINS;

    const int rstride = (gridDim.x >> 2) * (THREADS >> 2);   // rows per sweep
    const int cbase   = 4 * g + colq;                        // float2 col in row (of 16)

    int r = grp * (THREADS >> 2) + rowo;
    if (r >= nrows) return;

    float2 cur = X[r * 16 + cbase];
    for (; r < nrows; r += rstride) {
        int rn = r + rstride;
        float2 nxt = cur;
        if (rn < nrows) nxt = X[rn * 16 + cbase];    // prefetch
        float2 o;
        o.x = resolve(cur.x, P0, sc0, be0, ZL, qT0);
        o.y = resolve(cur.y, P1, sc1, be1, ZL, qT1);
        O[r * 16 + cbase] = o;
        cur = nxt;
    }
}

// ---------------- launch ------------------------------------------------------
extern "C" void kernel_launch(void* const* d_in, const int* in_sizes, int n_in,
                              void* d_out, int out_size) {
    const float* x = (const float*)d_in[0];
    const float* q = (const float*)d_in[1];
    float* out = (float*)d_out;
    const int nrows = in_sizes[0] / DIMS;

    cudaFuncSetAttribute(cdf_kernel, cudaFuncAttributeMaxDynamicSharedMemorySize,
                         SMEM_MAIN);

    int dev = 0;
    cudaGetDevice(&dev);
    int nsm = 148;
    cudaDeviceGetAttribute(&nsm, cudaDevAttrMultiProcessorCount, dev);
    int nblk = (nsm / 4) * 4;                 // multiple of 4 (dim groups)

    prep_kernel<<<DIMS, 256>>>(q);
    cdf_kernel<<<nblk, THREADS, SMEM_MAIN>>>((const float2*)x, (float2*)out, nrows);
}